// round 1
// baseline (speedup 1.0000x reference)
#include <cuda_runtime.h>
#include <cstdint>

#define N_USER 50000
#define N_ITEM 100000
#define NTOT   150000
#define NNZ    3000000
#define EMB    64
#define BATCH  4096

// Scratch state (device globals: no allocation allowed in kernel_launch)
__device__ __align__(16) float g_ego[(size_t)NTOT * EMB];
__device__ __align__(16) float g_side[(size_t)NTOT * EMB];
__device__ __align__(16) float g_total[(size_t)NTOT * EMB];

// ---------------------------------------------------------------------------
// init: ego = concat(user_emb, item_emb); total = ego; side = 0
// ---------------------------------------------------------------------------
__global__ void k_init(const float4* __restrict__ ue, const float4* __restrict__ ie) {
    int i = blockIdx.x * blockDim.x + threadIdx.x;   // over NTOT*16 float4s
    if (i >= NTOT * 16) return;
    float4 v = (i < N_USER * 16) ? ue[i] : ie[i - N_USER * 16];
    reinterpret_cast<float4*>(g_ego)[i]   = v;
    reinterpret_cast<float4*>(g_total)[i] = v;
    float4 z = make_float4(0.f, 0.f, 0.f, 0.f);
    reinterpret_cast<float4*>(g_side)[i]  = z;
}

// ---------------------------------------------------------------------------
// scatter: side[rows[e]] += vals[e] * ego[cols[e]]   (edge-parallel)
// One warp owns 32 consecutive edges (coalesced edge loads), then processes
// them 2 at a time: half-warp per edge, each lane a float4 (16 lanes * 16B =
// one 64-float row). Gather is an L2-resident LDG.128; scatter is
// red.global.add.v4.f32 (no return, spread addresses).
// ---------------------------------------------------------------------------
__global__ void k_scatter(const int* __restrict__ rows,
                          const int* __restrict__ cols,
                          const float* __restrict__ vals) {
    int w    = (blockIdx.x * blockDim.x + threadIdx.x) >> 5;
    int lane = threadIdx.x & 31;
    if (w >= NNZ / 32) return;               // NNZ % 32 == 0
    int base = w * 32;

    int   r = rows[base + lane];
    int   c = cols[base + lane];
    float v = vals[base + lane];

    int half = lane >> 4;     // which of the 2 edges this iteration
    int q    = lane & 15;     // float4 slot within the row

#pragma unroll
    for (int j = 0; j < 16; j++) {
        int   e  = 2 * j + half;
        int   ce = __shfl_sync(0xffffffffu, c, e);
        int   re = __shfl_sync(0xffffffffu, r, e);
        float ve = __shfl_sync(0xffffffffu, v, e);

        const float4 x = *reinterpret_cast<const float4*>(&g_ego[ce * EMB + q * 4]);
        float4 y;
        y.x = x.x * ve; y.y = x.y * ve; y.z = x.z * ve; y.w = x.w * ve;

        float* p = &g_side[re * EMB + q * 4];
        asm volatile("red.global.add.v4.f32 [%0], {%1,%2,%3,%4};"
                     :: "l"(p), "f"(y.x), "f"(y.y), "f"(y.z), "f"(y.w)
                     : "memory");
    }
}

// ---------------------------------------------------------------------------
// dense: ego = leaky_relu(side @ W + b, 0.2); total += ego / max(||ego||, eps)
// Also zeroes side in place (saves a separate clear pass for the next layer).
// One warp per row; lane owns 2 columns (float2). W staged in shared.
// ---------------------------------------------------------------------------
__global__ void k_dense(const float* __restrict__ W, const float* __restrict__ b) {
    __shared__ float Ws[EMB * EMB];
    __shared__ float bs[EMB];
    __shared__ float srow[8][EMB];

    int tid = threadIdx.x;
    for (int i = tid; i < EMB * EMB / 4; i += 256)
        reinterpret_cast<float4*>(Ws)[i] = reinterpret_cast<const float4*>(W)[i];
    if (tid < EMB) bs[tid] = b[tid];
    __syncthreads();

    int warp = tid >> 5, lane = tid & 31;
    int rowBase = blockIdx.x * 64 + warp * 8;

    for (int i = 0; i < 8; i++) {
        int r = rowBase + i;
        if (r >= NTOT) break;                 // uniform within warp

        // load my half-row of side, zero it for the next layer's scatter
        float2* sp = reinterpret_cast<float2*>(&g_side[r * EMB + lane * 2]);
        float2 s = *sp;
        *sp = make_float2(0.f, 0.f);
        reinterpret_cast<float2*>(srow[warp])[lane] = s;
        __syncwarp();

        float2 acc = *reinterpret_cast<const float2*>(&bs[lane * 2]);
#pragma unroll
        for (int k = 0; k < EMB; k++) {
            float  sk = srow[warp][k];                                        // LDS bcast
            float2 wk = *reinterpret_cast<const float2*>(&Ws[k * EMB + lane * 2]);
            acc.x += sk * wk.x;
            acc.y += sk * wk.y;
        }

        float2 e;
        e.x = acc.x > 0.f ? acc.x : 0.2f * acc.x;
        e.y = acc.y > 0.f ? acc.y : 0.2f * acc.y;

        *reinterpret_cast<float2*>(&g_ego[r * EMB + lane * 2]) = e;

        float ss = e.x * e.x + e.y * e.y;
#pragma unroll
        for (int off = 16; off; off >>= 1)
            ss += __shfl_xor_sync(0xffffffffu, ss, off);
        float denom = fmaxf(sqrtf(ss), 1e-12f);

        float2* tp = reinterpret_cast<float2*>(&g_total[r * EMB + lane * 2]);
        float2 t = *tp;
        t.x += e.x / denom;
        t.y += e.y / denom;
        *tp = t;
    }
}

// ---------------------------------------------------------------------------
// output gather: out[i] = total[users[i]]
// ---------------------------------------------------------------------------
__global__ void k_out(const int* __restrict__ users, float4* __restrict__ out) {
    int i = blockIdx.x * blockDim.x + threadIdx.x;  // BATCH*16 float4s
    if (i >= BATCH * 16) return;
    int bidx = i >> 4, q = i & 15;
    int u = users[bidx];
    out[i] = reinterpret_cast<const float4*>(g_total)[u * 16 + q];
}

// ---------------------------------------------------------------------------
extern "C" void kernel_launch(void* const* d_in, const int* in_sizes, int n_in,
                              void* d_out, int out_size) {
    const int*   users = (const int*)d_in[0];
    const int*   rows  = (const int*)d_in[1];
    const int*   cols  = (const int*)d_in[2];
    const float* vals  = (const float*)d_in[3];
    const float* ue    = (const float*)d_in[4];
    const float* ie    = (const float*)d_in[5];
    const float* Wl[3] = {(const float*)d_in[6], (const float*)d_in[8],  (const float*)d_in[10]};
    const float* Bl[3] = {(const float*)d_in[7], (const float*)d_in[9],  (const float*)d_in[11]};

    k_init<<<(NTOT * 16 + 255) / 256, 256>>>((const float4*)ue, (const float4*)ie);

    for (int l = 0; l < 3; l++) {
        k_scatter<<<(NNZ / 32 + 7) / 8, 256>>>(rows, cols, vals);
        k_dense<<<(NTOT + 63) / 64, 256>>>(Wl[l], Bl[l]);
    }

    k_out<<<(BATCH * 16 + 255) / 256, 256>>>(users, (float4*)d_out);
}

// round 2
// speedup vs baseline: 1.8690x; 1.8690x over previous
#include <cuda_runtime.h>
#include <cstdint>

#define N_USER 50000
#define N_ITEM 100000
#define NTOT   150000
#define NNZ    3000000
#define EMB    64
#define BATCH  4096
#define NBLK_SCAN 147   // ceil(150000/1024)

// ---------------- device scratch (no allocation allowed) --------------------
__device__ __align__(16) float g_egoA[(size_t)NTOT * EMB];
__device__ __align__(16) float g_egoB[(size_t)NTOT * EMB];
__device__ __align__(16) float g_total[(size_t)NTOT * EMB];
__device__ unsigned long long g_edges[NNZ];   // {col (lo 32), val bits (hi 32)}
__device__ int g_cnt[NTOT];
__device__ int g_start[NTOT];
__device__ int g_cur[NTOT];
__device__ int g_bsum[NBLK_SCAN];

// ---------------------------------------------------------------------------
// init: egoA = concat(user_emb, item_emb); total = egoA; cnt = 0
// ---------------------------------------------------------------------------
__global__ void k_init(const float4* __restrict__ ue, const float4* __restrict__ ie) {
    int i = blockIdx.x * blockDim.x + threadIdx.x;   // NTOT*16 float4s
    if (i < NTOT) g_cnt[i] = 0;
    if (i >= NTOT * 16) return;
    float4 v = (i < N_USER * 16) ? ue[i] : ie[i - N_USER * 16];
    reinterpret_cast<float4*>(g_egoA)[i]  = v;
    reinterpret_cast<float4*>(g_total)[i] = v;
}

// ---------------------------------------------------------------------------
// CSR build: histogram -> exclusive scan -> permute edges into row order
// ---------------------------------------------------------------------------
__global__ void k_hist(const int* __restrict__ rows) {
    int i = blockIdx.x * blockDim.x + threadIdx.x;
    if (i < NNZ) atomicAdd(&g_cnt[rows[i]], 1);
}

__global__ void k_scanA() {
    __shared__ int s[1024];
    int t = threadIdx.x;
    int g = blockIdx.x * 1024 + t;
    int v = (g < NTOT) ? g_cnt[g] : 0;
    s[t] = v;
    __syncthreads();
#pragma unroll
    for (int off = 1; off < 1024; off <<= 1) {
        int add = (t >= off) ? s[t - off] : 0;
        __syncthreads();
        s[t] += add;
        __syncthreads();
    }
    if (g < NTOT) g_start[g] = s[t] - v;          // exclusive
    if (t == 1023) g_bsum[blockIdx.x] = s[1023];  // block total
}

__global__ void k_scanB() {   // 1 thread: scan 147 block sums
    int run = 0;
    for (int b = 0; b < NBLK_SCAN; b++) {
        int t = g_bsum[b];
        g_bsum[b] = run;
        run += t;
    }
}

__global__ void k_scanC() {
    int g = blockIdx.x * 1024 + threadIdx.x;
    if (g >= NTOT) return;
    int off = g_start[g] + g_bsum[blockIdx.x];
    g_start[g] = off;
    g_cur[g]   = off;
}

__global__ void k_fill(const int* __restrict__ rows, const int* __restrict__ cols,
                       const float* __restrict__ vals) {
    int i = blockIdx.x * blockDim.x + threadIdx.x;
    if (i >= NNZ) return;
    int r = rows[i];
    int p = atomicAdd(&g_cur[r], 1);
    g_edges[p] = (unsigned long long)(unsigned)cols[i]
               | ((unsigned long long)__float_as_uint(vals[i]) << 32);
}

// ---------------------------------------------------------------------------
// fused layer: per row r:
//   side = sum_e val[e] * ego_in[col[e]]          (segmented gather, registers)
//   ego_out = leaky_relu(side @ W + b, 0.2)
//   total  += ego_out / max(||ego_out||, 1e-12)
// Warp = 4 rows. Lane owns cols {2*lane, 2*lane+1} (float2, coalesced 256B).
// ---------------------------------------------------------------------------
__global__ void __launch_bounds__(256)
k_layer(const float* __restrict__ ego_in, float* __restrict__ ego_out,
        const float* __restrict__ W, const float* __restrict__ b) {
    __shared__ float Ws[EMB * EMB];
    __shared__ float srow[8][EMB][4];   // [warp][k][row-in-group]

    int tid = threadIdx.x;
    for (int i = tid; i < EMB * EMB / 4; i += 256)
        reinterpret_cast<float4*>(Ws)[i] = reinterpret_cast<const float4*>(W)[i];
    __syncthreads();

    int warp = tid >> 5, lane = tid & 31;
    int r0 = (blockIdx.x * 8 + warp) * 4;
    if (r0 >= NTOT) return;

    // ---- phase 1: segmented gather for 4 rows ----
#pragma unroll
    for (int r = 0; r < 4; r++) {
        int row   = r0 + r;
        int start = g_start[row];
        int n     = g_cnt[row];
        float2 acc = make_float2(0.f, 0.f);

        for (int base = 0; base < n; base += 32) {
            unsigned long long em = 0ull;
            if (base + lane < n) em = g_edges[start + base + lane];
            int m = min(32, n - base);
            int j = 0;
            for (; j + 4 <= m; j += 4) {
                unsigned long long e0 = __shfl_sync(0xffffffffu, em, j);
                unsigned long long e1 = __shfl_sync(0xffffffffu, em, j + 1);
                unsigned long long e2 = __shfl_sync(0xffffffffu, em, j + 2);
                unsigned long long e3 = __shfl_sync(0xffffffffu, em, j + 3);
                const float2 x0 = *reinterpret_cast<const float2*>(
                    &ego_in[(size_t)(unsigned)(e0 & 0xffffffffu) * EMB + 2 * lane]);
                const float2 x1 = *reinterpret_cast<const float2*>(
                    &ego_in[(size_t)(unsigned)(e1 & 0xffffffffu) * EMB + 2 * lane]);
                const float2 x2 = *reinterpret_cast<const float2*>(
                    &ego_in[(size_t)(unsigned)(e2 & 0xffffffffu) * EMB + 2 * lane]);
                const float2 x3 = *reinterpret_cast<const float2*>(
                    &ego_in[(size_t)(unsigned)(e3 & 0xffffffffu) * EMB + 2 * lane]);
                float v0 = __int_as_float((int)(e0 >> 32));
                float v1 = __int_as_float((int)(e1 >> 32));
                float v2 = __int_as_float((int)(e2 >> 32));
                float v3 = __int_as_float((int)(e3 >> 32));
                acc.x += v0 * x0.x; acc.y += v0 * x0.y;
                acc.x += v1 * x1.x; acc.y += v1 * x1.y;
                acc.x += v2 * x2.x; acc.y += v2 * x2.y;
                acc.x += v3 * x3.x; acc.y += v3 * x3.y;
            }
            for (; j < m; j++) {
                unsigned long long e = __shfl_sync(0xffffffffu, em, j);
                const float2 x = *reinterpret_cast<const float2*>(
                    &ego_in[(size_t)(unsigned)(e & 0xffffffffu) * EMB + 2 * lane]);
                float v = __int_as_float((int)(e >> 32));
                acc.x += v * x.x; acc.y += v * x.y;
            }
        }
        srow[warp][2 * lane][r]     = acc.x;
        srow[warp][2 * lane + 1][r] = acc.y;
    }
    __syncwarp();

    // ---- phase 2: batched 4-row matmul (W in smem) ----
    const float2 bias = *reinterpret_cast<const float2*>(&b[2 * lane]);
    float2 o0 = bias, o1 = bias, o2 = bias, o3 = bias;
#pragma unroll
    for (int k = 0; k < EMB; k++) {
        float4 s4 = *reinterpret_cast<const float4*>(&srow[warp][k][0]);  // broadcast
        float2 wk = *reinterpret_cast<const float2*>(&Ws[k * EMB + 2 * lane]);
        o0.x += s4.x * wk.x; o0.y += s4.x * wk.y;
        o1.x += s4.y * wk.x; o1.y += s4.y * wk.y;
        o2.x += s4.z * wk.x; o2.y += s4.z * wk.y;
        o3.x += s4.w * wk.x; o3.y += s4.w * wk.y;
    }

    // ---- phase 3: leaky_relu, write ego_out, l2norm accumulate into total ----
    float2 os[4] = {o0, o1, o2, o3};
#pragma unroll
    for (int r = 0; r < 4; r++) {
        int row = r0 + r;
        float2 e;
        e.x = os[r].x > 0.f ? os[r].x : 0.2f * os[r].x;
        e.y = os[r].y > 0.f ? os[r].y : 0.2f * os[r].y;

        *reinterpret_cast<float2*>(&ego_out[(size_t)row * EMB + 2 * lane]) = e;

        float ss = e.x * e.x + e.y * e.y;
#pragma unroll
        for (int off = 16; off; off >>= 1)
            ss += __shfl_xor_sync(0xffffffffu, ss, off);
        float inv = 1.f / fmaxf(sqrtf(ss), 1e-12f);

        float2* tp = reinterpret_cast<float2*>(&g_total[(size_t)row * EMB + 2 * lane]);
        float2 t = *tp;
        t.x += e.x * inv;
        t.y += e.y * inv;
        *tp = t;
    }
}

// ---------------------------------------------------------------------------
// output gather: out[i] = total[users[i]]
// ---------------------------------------------------------------------------
__global__ void k_out(const int* __restrict__ users, float4* __restrict__ out) {
    int i = blockIdx.x * blockDim.x + threadIdx.x;  // BATCH*16 float4s
    if (i >= BATCH * 16) return;
    int bidx = i >> 4, q = i & 15;
    int u = users[bidx];
    out[i] = reinterpret_cast<const float4*>(g_total)[(size_t)u * 16 + q];
}

// ---------------------------------------------------------------------------
extern "C" void kernel_launch(void* const* d_in, const int* in_sizes, int n_in,
                              void* d_out, int out_size) {
    const int*   users = (const int*)d_in[0];
    const int*   rows  = (const int*)d_in[1];
    const int*   cols  = (const int*)d_in[2];
    const float* vals  = (const float*)d_in[3];
    const float* ue    = (const float*)d_in[4];
    const float* ie    = (const float*)d_in[5];
    const float* Wl[3] = {(const float*)d_in[6], (const float*)d_in[8],  (const float*)d_in[10]};
    const float* Bl[3] = {(const float*)d_in[7], (const float*)d_in[9],  (const float*)d_in[11]};

    float *egoA, *egoB;
    cudaGetSymbolAddress((void**)&egoA, g_egoA);
    cudaGetSymbolAddress((void**)&egoB, g_egoB);

    k_init<<<(NTOT * 16 + 255) / 256, 256>>>((const float4*)ue, (const float4*)ie);

    // CSR build
    k_hist<<<(NNZ + 255) / 256, 256>>>(rows);
    k_scanA<<<NBLK_SCAN, 1024>>>();
    k_scanB<<<1, 1>>>();
    k_scanC<<<NBLK_SCAN, 1024>>>();
    k_fill<<<(NNZ + 255) / 256, 256>>>(rows, cols, vals);

    // 3 fused layers, ping-pong ego buffers
    const int LG = (NTOT / 4 + 8 - 1) / 8 + 1;   // warps of 4 rows, 8 warps/block
    float* bufs[4] = {egoA, egoB, egoA, egoB};
    for (int l = 0; l < 3; l++)
        k_layer<<<(NTOT / 32 + 1), 256>>>(bufs[l], bufs[l + 1], Wl[l], Bl[l]);
    (void)LG;

    k_out<<<(BATCH * 16 + 255) / 256, 256>>>(users, (float4*)d_out);
}

// round 3
// speedup vs baseline: 2.0024x; 1.0713x over previous
#include <cuda_runtime.h>
#include <cuda_fp16.h>
#include <cstdint>

#define N_USER 50000
#define N_ITEM 100000
#define NTOT   150000
#define NNZ    3000000
#define EMB    64
#define BATCH  4096
#define NBLK_SCAN 147   // ceil(150000/1024)

// ---------------- device scratch (no allocation allowed) --------------------
__device__ __align__(16) __half2 g_egoA[(size_t)NTOT * 32];   // fp16 ego ping
__device__ __align__(16) __half2 g_egoB[(size_t)NTOT * 32];   // fp16 ego pong
__device__ __align__(16) float   g_total[(size_t)NTOT * EMB]; // fp32 accumulator
__device__ __align__(16) unsigned long long g_edges[NNZ];     // {col lo32, val hi32}
__device__ int g_cnt[NTOT];
__device__ int g_start[NTOT];
__device__ int g_cur[NTOT];
__device__ int g_bsum[NBLK_SCAN];

// ---------------------------------------------------------------------------
// init: total = concat(user_emb, item_emb) (fp32); egoA = fp16(same); cnt = 0
// ---------------------------------------------------------------------------
__global__ void k_init(const float4* __restrict__ ue, const float4* __restrict__ ie) {
    int i = blockIdx.x * blockDim.x + threadIdx.x;   // NTOT*16 float4s
    if (i < NTOT) g_cnt[i] = 0;
    if (i >= NTOT * 16) return;
    float4 v = (i < N_USER * 16) ? ue[i] : ie[i - N_USER * 16];
    reinterpret_cast<float4*>(g_total)[i] = v;
    g_egoA[2 * i]     = __floats2half2_rn(v.x, v.y);
    g_egoA[2 * i + 1] = __floats2half2_rn(v.z, v.w);
}

// ---------------------------------------------------------------------------
// CSR build: histogram -> exclusive scan -> permute edges into row order
// ---------------------------------------------------------------------------
__global__ void k_hist(const int* __restrict__ rows) {
    int i = blockIdx.x * blockDim.x + threadIdx.x;
    if (i < NNZ) atomicAdd(&g_cnt[rows[i]], 1);
}

__global__ void k_scanA() {
    __shared__ int s[1024];
    int t = threadIdx.x;
    int g = blockIdx.x * 1024 + t;
    int v = (g < NTOT) ? g_cnt[g] : 0;
    s[t] = v;
    __syncthreads();
#pragma unroll
    for (int off = 1; off < 1024; off <<= 1) {
        int add = (t >= off) ? s[t - off] : 0;
        __syncthreads();
        s[t] += add;
        __syncthreads();
    }
    if (g < NTOT) g_start[g] = s[t] - v;          // exclusive within block
    if (t == 1023) g_bsum[blockIdx.x] = s[1023];  // block total
}

__global__ void k_scanB() {   // one block of 256 threads: scan 147 block sums
    __shared__ int s[256];
    int t = threadIdx.x;
    int v = (t < NBLK_SCAN) ? g_bsum[t] : 0;
    s[t] = v;
    __syncthreads();
#pragma unroll
    for (int off = 1; off < 256; off <<= 1) {
        int add = (t >= off) ? s[t - off] : 0;
        __syncthreads();
        s[t] += add;
        __syncthreads();
    }
    if (t < NBLK_SCAN) g_bsum[t] = s[t] - v;      // exclusive
}

__global__ void k_scanC() {
    int g = blockIdx.x * 1024 + threadIdx.x;
    if (g >= NTOT) return;
    int off = g_start[g] + g_bsum[blockIdx.x];
    g_start[g] = off;
    g_cur[g]   = off;
}

__global__ void k_fill(const int* __restrict__ rows, const int* __restrict__ cols,
                       const float* __restrict__ vals) {
    int i = blockIdx.x * blockDim.x + threadIdx.x;
    if (i >= NNZ) return;
    int r = rows[i];
    int p = atomicAdd(&g_cur[r], 1);
    g_edges[p] = (unsigned long long)(unsigned)cols[i]
               | ((unsigned long long)__float_as_uint(vals[i]) << 32);
}

// ---------------------------------------------------------------------------
// fused layer. Per row r:
//   side    = sum_e val[e] * ego_in[col[e]]     (fp16 gather, fp32 acc)
//   ego_out = fp16( leaky_relu(side @ W + b, 0.2) )
//   total  += relu_out / max(||relu_out||, 1e-12)   (fp32)
// Warp = 4 rows; lane owns cols {2l, 2l+1}. Edge words are broadcast-loaded
// by all lanes (uniform LDG, 1 sector; 4 consecutive words share a sector).
// Row gather = 32 lanes x half2 = 128B = one L1 wavefront.
// ---------------------------------------------------------------------------
__global__ void __launch_bounds__(256)
k_layer(const __half2* __restrict__ ego_in, __half2* __restrict__ ego_out,
        const float* __restrict__ W, const float* __restrict__ b) {
    __shared__ float Ws[EMB * EMB];
    __shared__ float srow[8][EMB][4];   // [warp][k][row-in-group]

    int tid = threadIdx.x;
    for (int i = tid; i < EMB * EMB / 4; i += 256)
        reinterpret_cast<float4*>(Ws)[i] = reinterpret_cast<const float4*>(W)[i];
    __syncthreads();

    int warp = tid >> 5, lane = tid & 31;
    int r0 = (blockIdx.x * 8 + warp) * 4;
    if (r0 >= NTOT) return;

    // ---- phase 1: segmented gather, 4 rows ----
#pragma unroll
    for (int r = 0; r < 4; r++) {
        int row = r0 + r;
        float2 acc = make_float2(0.f, 0.f);
        if (row < NTOT) {
            int start = g_start[row];
            int n     = g_cnt[row];
            const unsigned long long* ep = &g_edges[start];
            int j = 0;
            for (; j + 4 <= n; j += 4) {
                unsigned long long e0 = ep[j];
                unsigned long long e1 = ep[j + 1];
                unsigned long long e2 = ep[j + 2];
                unsigned long long e3 = ep[j + 3];
                __half2 x0 = ego_in[(size_t)(unsigned)e0 * 32 + lane];
                __half2 x1 = ego_in[(size_t)(unsigned)e1 * 32 + lane];
                __half2 x2 = ego_in[(size_t)(unsigned)e2 * 32 + lane];
                __half2 x3 = ego_in[(size_t)(unsigned)e3 * 32 + lane];
                float v0 = __uint_as_float((unsigned)(e0 >> 32));
                float v1 = __uint_as_float((unsigned)(e1 >> 32));
                float v2 = __uint_as_float((unsigned)(e2 >> 32));
                float v3 = __uint_as_float((unsigned)(e3 >> 32));
                float2 f0 = __half22float2(x0);
                float2 f1 = __half22float2(x1);
                float2 f2 = __half22float2(x2);
                float2 f3 = __half22float2(x3);
                acc.x += v0 * f0.x; acc.y += v0 * f0.y;
                acc.x += v1 * f1.x; acc.y += v1 * f1.y;
                acc.x += v2 * f2.x; acc.y += v2 * f2.y;
                acc.x += v3 * f3.x; acc.y += v3 * f3.y;
            }
            for (; j < n; j++) {
                unsigned long long e = ep[j];
                __half2 x = ego_in[(size_t)(unsigned)e * 32 + lane];
                float  v = __uint_as_float((unsigned)(e >> 32));
                float2 f = __half22float2(x);
                acc.x += v * f.x; acc.y += v * f.y;
            }
        }
        srow[warp][2 * lane][r]     = acc.x;
        srow[warp][2 * lane + 1][r] = acc.y;
    }
    __syncwarp();

    // ---- phase 2: batched 4-row matmul (W in smem) ----
    const float2 bias = *reinterpret_cast<const float2*>(&b[2 * lane]);
    float2 o0 = bias, o1 = bias, o2 = bias, o3 = bias;
#pragma unroll
    for (int k = 0; k < EMB; k++) {
        float4 s4 = *reinterpret_cast<const float4*>(&srow[warp][k][0]);  // bcast
        float2 wk = *reinterpret_cast<const float2*>(&Ws[k * EMB + 2 * lane]);
        o0.x += s4.x * wk.x; o0.y += s4.x * wk.y;
        o1.x += s4.y * wk.x; o1.y += s4.y * wk.y;
        o2.x += s4.z * wk.x; o2.y += s4.z * wk.y;
        o3.x += s4.w * wk.x; o3.y += s4.w * wk.y;
    }

    // ---- phase 3: leaky_relu, write fp16 ego_out, l2norm accumulate ----
    float2 os[4] = {o0, o1, o2, o3};
#pragma unroll
    for (int r = 0; r < 4; r++) {
        int row = r0 + r;
        if (row >= NTOT) break;
        float2 e;
        e.x = os[r].x > 0.f ? os[r].x : 0.2f * os[r].x;
        e.y = os[r].y > 0.f ? os[r].y : 0.2f * os[r].y;

        ego_out[(size_t)row * 32 + lane] = __floats2half2_rn(e.x, e.y);

        float ss = e.x * e.x + e.y * e.y;
#pragma unroll
        for (int off = 16; off; off >>= 1)
            ss += __shfl_xor_sync(0xffffffffu, ss, off);
        float inv = 1.f / fmaxf(sqrtf(ss), 1e-12f);

        float2* tp = reinterpret_cast<float2*>(&g_total[(size_t)row * EMB + 2 * lane]);
        float2 t = *tp;
        t.x += e.x * inv;
        t.y += e.y * inv;
        *tp = t;
    }
}

// ---------------------------------------------------------------------------
// output gather: out[i] = total[users[i]]
// ---------------------------------------------------------------------------
__global__ void k_out(const int* __restrict__ users, float4* __restrict__ out) {
    int i = blockIdx.x * blockDim.x + threadIdx.x;  // BATCH*16 float4s
    if (i >= BATCH * 16) return;
    int bidx = i >> 4, q = i & 15;
    int u = users[bidx];
    out[i] = reinterpret_cast<const float4*>(g_total)[(size_t)u * 16 + q];
}

// ---------------------------------------------------------------------------
extern "C" void kernel_launch(void* const* d_in, const int* in_sizes, int n_in,
                              void* d_out, int out_size) {
    const int*   users = (const int*)d_in[0];
    const int*   rows  = (const int*)d_in[1];
    const int*   cols  = (const int*)d_in[2];
    const float* vals  = (const float*)d_in[3];
    const float* ue    = (const float*)d_in[4];
    const float* ie    = (const float*)d_in[5];
    const float* Wl[3] = {(const float*)d_in[6], (const float*)d_in[8],  (const float*)d_in[10]};
    const float* Bl[3] = {(const float*)d_in[7], (const float*)d_in[9],  (const float*)d_in[11]};

    __half2 *egoA, *egoB;
    cudaGetSymbolAddress((void**)&egoA, g_egoA);
    cudaGetSymbolAddress((void**)&egoB, g_egoB);

    k_init<<<(NTOT * 16 + 255) / 256, 256>>>((const float4*)ue, (const float4*)ie);

    // CSR build
    k_hist<<<(NNZ + 255) / 256, 256>>>(rows);
    k_scanA<<<NBLK_SCAN, 1024>>>();
    k_scanB<<<1, 256>>>();
    k_scanC<<<NBLK_SCAN, 1024>>>();
    k_fill<<<(NNZ + 255) / 256, 256>>>(rows, cols, vals);

    // 3 fused layers, ping-pong fp16 ego buffers
    __half2* bufs[4] = {egoA, egoB, egoA, egoB};
    for (int l = 0; l < 3; l++)
        k_layer<<<(NTOT + 31) / 32, 256>>>(bufs[l], bufs[l + 1], Wl[l], Bl[l]);

    k_out<<<(BATCH * 16 + 255) / 256, 256>>>(users, (float4*)d_out);
}